// round 11
// baseline (speedup 1.0000x reference)
#include <cuda_runtime.h>

// out[i,j,k] = C[i,j,k] * x[i,j]
// B=4096, INPUT_SIZE=512, EMBED_DIM=64 -> n = 2^27 floats, n4 = 2^25 float4
//
// v11: winning R6 geometry (512 thr x 8 float4, 64KB block tiles, ldcs/stcs),
// with a 2-stage software pipeline: load half-tile 0, then overlap
// {store half k, load half k+1}. Removes the per-thread read-only head /
// write-only tail so the MC sees a steadier read/write mix.

#define THREADS 512
#define UNROLL  8
#define HALF    (UNROLL / 2)

__global__ __launch_bounds__(THREADS)
void bcast_mul_exact(const float* __restrict__ x,
                     const float4* __restrict__ C4,
                     float4* __restrict__ out4) {
    const unsigned base = blockIdx.x * (THREADS * UNROLL) + threadIdx.x;

    float4 c0[HALF], c1[HALF];
    float  s0[HALF], s1[HALF];

    // Prologue: load first half.
#pragma unroll
    for (int j = 0; j < HALF; j++) {
        unsigned i = base + j * THREADS;
        c0[j] = __ldcs(&C4[i]);
        s0[j] = __ldg(&x[i >> 4]);
    }

    // Stage 2 loads overlap stage 1 stores.
#pragma unroll
    for (int j = 0; j < HALF; j++) {
        unsigned i = base + (HALF + j) * THREADS;
        c1[j] = __ldcs(&C4[i]);
        s1[j] = __ldg(&x[i >> 4]);
    }
#pragma unroll
    for (int j = 0; j < HALF; j++) {
        unsigned i = base + j * THREADS;
        float4 o;
        o.x = c0[j].x * s0[j];
        o.y = c0[j].y * s0[j];
        o.z = c0[j].z * s0[j];
        o.w = c0[j].w * s0[j];
        __stcs(&out4[i], o);
    }

    // Epilogue: store second half.
#pragma unroll
    for (int j = 0; j < HALF; j++) {
        unsigned i = base + (HALF + j) * THREADS;
        float4 o;
        o.x = c1[j].x * s1[j];
        o.y = c1[j].y * s1[j];
        o.z = c1[j].z * s1[j];
        o.w = c1[j].w * s1[j];
        __stcs(&out4[i], o);
    }
}

__global__ void bcast_mul_generic(const float* __restrict__ x,
                                  const float4* __restrict__ C4,
                                  float4* __restrict__ out4,
                                  unsigned n4) {
    unsigned i = blockIdx.x * blockDim.x + threadIdx.x;
    if (i < n4) {
        float s = __ldg(&x[i >> 4]);
        float4 c = __ldcs(&C4[i]);
        float4 o;
        o.x = c.x * s; o.y = c.y * s; o.z = c.z * s; o.w = c.w * s;
        __stcs(&out4[i], o);
    }
}

extern "C" void kernel_launch(void* const* d_in, const int* in_sizes, int n_in,
                              void* d_out, int out_size) {
    const float* x;
    const float* C;
    if (in_sizes[0] < in_sizes[1]) {
        x = (const float*)d_in[0];
        C = (const float*)d_in[1];
    } else {
        x = (const float*)d_in[1];
        C = (const float*)d_in[0];
    }

    unsigned n4 = (unsigned)((long long)out_size >> 2);   // 33,554,432
    const unsigned per_block = THREADS * UNROLL;          // 4096

    if (n4 % per_block == 0) {
        bcast_mul_exact<<<n4 / per_block, THREADS>>>(
            x, (const float4*)C, (float4*)d_out);
    } else {
        bcast_mul_generic<<<(n4 + 255) / 256, 256>>>(
            x, (const float4*)C, (float4*)d_out, n4);
    }
}